// round 1
// baseline (speedup 1.0000x reference)
#include <cuda_runtime.h>

// Problem constants
#define SQ   2048          // sequence length
#define NH   16            // heads
#define HD   64            // head dim
#define DIN  1024          // model dim
#define MALL 4096          // B*S rows

// Scratch (device globals; no runtime allocation allowed)
__device__ float g_Qc[NH * SQ * 128];                  // [h][s][b*64+d]  (Q0|Q1)   16MB
__device__ float g_Kc[NH * SQ * 128];                  // [h][s][b*64+d]  (K0|-K1)  16MB
__device__ float g_Vc[NH * SQ * 128];                  // [h][s][b*64+d]  (V0|V1)   16MB
__device__ float g_Attn[(size_t)NH * SQ * SQ];         // [h][q][k] sigmoid probs  256MB
__device__ float g_Vals[2 * SQ * DIN];                 // [b][s][h*64+d]            16MB
__device__ float g_Colsum[NH * HD];                    // sum_k V1[h][k][d]

// ---------------------------------------------------------------------------
// Shared 128x128 tile SGEMM core. 256 threads, each computes 8x8.
// BT=false: C = A[MxK] * B[KxN] (both row-major)
// BT=true : C = A[MxK] * B[NxK]^T (both row-major)  — used for Q*K^T
// K must be a multiple of 8; all tile dims assumed in-bounds (our dims are
// multiples of 128 / N>=128 padded exactly).
// ---------------------------------------------------------------------------
template <bool BT>
__device__ __forceinline__ void gemm_tile(
    const float* __restrict__ A, int lda,
    const float* __restrict__ B, int ldb,
    int K, int m0, int n0, float acc[8][8])
{
    __shared__ float As[8][128];
    __shared__ float Bs[8][128];

    const int tid   = threadIdx.x;
    const int a_row = tid >> 1;            // 0..127
    const int a_col = (tid & 1) << 2;      // 0 or 4
    const int tx    = tid & 15;
    const int ty    = tid >> 4;

    for (int k0 = 0; k0 < K; k0 += 8) {
        // load + transpose A tile (BMxBK -> As[k][m])
        float4 a = *(const float4*)(A + (size_t)(m0 + a_row) * lda + k0 + a_col);
        As[a_col + 0][a_row] = a.x;
        As[a_col + 1][a_row] = a.y;
        As[a_col + 2][a_row] = a.z;
        As[a_col + 3][a_row] = a.w;

        if (BT) {
            // B tile rows are N, cols are K -> transpose into Bs[k][n]
            const int b_row = tid >> 1;          // n within tile
            const int b_col = (tid & 1) << 2;    // k within tile
            float4 b = *(const float4*)(B + (size_t)(n0 + b_row) * ldb + k0 + b_col);
            Bs[b_col + 0][b_row] = b.x;
            Bs[b_col + 1][b_row] = b.y;
            Bs[b_col + 2][b_row] = b.z;
            Bs[b_col + 3][b_row] = b.w;
        } else {
            const int b_row = tid >> 5;          // k within tile (0..7)
            const int b_col = (tid & 31) << 2;   // n within tile
            float4 b = *(const float4*)(B + (size_t)(k0 + b_row) * ldb + n0 + b_col);
            *(float4*)(&Bs[b_row][b_col]) = b;
        }
        __syncthreads();

#pragma unroll
        for (int kk = 0; kk < 8; ++kk) {
            float ra[8], rb[8];
#pragma unroll
            for (int i = 0; i < 8; ++i) ra[i] = As[kk][ty * 8 + i];
#pragma unroll
            for (int j = 0; j < 8; ++j) rb[j] = Bs[kk][tx * 8 + j];
#pragma unroll
            for (int i = 0; i < 8; ++i)
#pragma unroll
                for (int j = 0; j < 8; ++j)
                    acc[i][j] = fmaf(ra[i], rb[j], acc[i][j]);
        }
        __syncthreads();
    }
}

// ---------------------------------------------------------------------------
// 1) Projections: q/k/v = x @ w_{q,k,v}, scattered into per-head concat layout
//    z = 0 -> Qc (+), 1 -> Kc (negate batch 1), 2 -> Vc (+)
// ---------------------------------------------------------------------------
__global__ __launch_bounds__(256) void proj_kernel(
    const float* __restrict__ x,
    const float* __restrict__ wq,
    const float* __restrict__ wk,
    const float* __restrict__ wv)
{
    const int z = blockIdx.z;
    const float* W = (z == 0) ? wq : (z == 1) ? wk : wv;
    float* dst     = (z == 0) ? g_Qc : (z == 1) ? g_Kc : g_Vc;

    const int m0 = blockIdx.y * 128;
    const int n0 = blockIdx.x * 128;
    float acc[8][8] = {};
    gemm_tile<false>(x, DIN, W, DIN, DIN, m0, n0, acc);

    const int tx = threadIdx.x & 15, ty = threadIdx.x >> 4;
#pragma unroll
    for (int i = 0; i < 8; ++i) {
        const int m = m0 + ty * 8 + i;
        const int b = m >> 11;            // batch
        const int s = m & 2047;           // seq pos
#pragma unroll
        for (int j = 0; j < 8; ++j) {
            const int n = n0 + tx * 8 + j;
            const int h = n >> 6;
            const int d = n & 63;
            float v = acc[i][j];
            if (z == 1 && b == 1) v = -v;
            dst[(size_t)((h << 11) + s) * 128 + (b << 6) + d] = v;
        }
    }
}

// ---------------------------------------------------------------------------
// colsum of V1 per head: g_Colsum[h][d] = sum_k Vc[h][k][64+d]
// ---------------------------------------------------------------------------
__global__ void colsum_kernel()
{
    const int h = blockIdx.x;
    const int d = threadIdx.x;  // 64 threads
    const float* v = g_Vc + (size_t)h * SQ * 128 + 64 + d;
    float s = 0.f;
    for (int k = 0; k < SQ; ++k) s += v[(size_t)k * 128];
    g_Colsum[h * HD + d] = s;
}

// ---------------------------------------------------------------------------
// 2) Scores (NT, K=128): D = Qc @ Kc^T = s0 - s1; store sigmoid(D / 32)
// ---------------------------------------------------------------------------
__global__ __launch_bounds__(256) void score_kernel()
{
    const int h = blockIdx.z;
    const float* A = g_Qc + (size_t)h * SQ * 128;
    const float* B = g_Kc + (size_t)h * SQ * 128;
    float* C       = g_Attn + (size_t)h * SQ * SQ;

    const int m0 = blockIdx.y * 128;
    const int n0 = blockIdx.x * 128;
    float acc[8][8] = {};
    gemm_tile<true>(A, 128, B, 128, 128, m0, n0, acc);

    const int tx = threadIdx.x & 15, ty = threadIdx.x >> 4;
    const float inv_scale = 1.0f / 32.0f;
#pragma unroll
    for (int i = 0; i < 8; ++i) {
        const int m = m0 + ty * 8 + i;
#pragma unroll
        for (int j = 0; j < 8; ++j) {
            const int n = n0 + tx * 8 + j;
            const float xv = acc[i][j] * inv_scale;
            C[(size_t)m * SQ + n] = 1.0f / (1.0f + __expf(-xv));
        }
    }
}

// ---------------------------------------------------------------------------
// 3) PV (NN, N=128): P = Attn @ Vc. n<64 -> vals0, n>=64 -> colsum - P (vals1)
// ---------------------------------------------------------------------------
__global__ __launch_bounds__(256) void pv_kernel()
{
    const int h = blockIdx.z;
    const float* A = g_Attn + (size_t)h * SQ * SQ;   // [2048 x 2048]
    const float* B = g_Vc + (size_t)h * SQ * 128;    // [2048 x 128]

    const int m0 = blockIdx.y * 128;
    const int n0 = 0;
    float acc[8][8] = {};
    gemm_tile<false>(A, SQ, B, 128, SQ, m0, n0, acc);

    const int tx = threadIdx.x & 15, ty = threadIdx.x >> 4;
#pragma unroll
    for (int i = 0; i < 8; ++i) {
        const int q = m0 + ty * 8 + i;
#pragma unroll
        for (int j = 0; j < 8; ++j) {
            const int n = tx * 8 + j;        // 0..127
            if (n < 64) {
                g_Vals[(size_t)q * DIN + h * 64 + n] = acc[i][j];
            } else {
                const int d = n - 64;
                g_Vals[(size_t)(SQ + q) * DIN + h * 64 + d] =
                    g_Colsum[h * HD + d] - acc[i][j];
            }
        }
    }
}

// ---------------------------------------------------------------------------
// 4) Output projection: out = Vals @ W_o
// ---------------------------------------------------------------------------
__global__ __launch_bounds__(256) void out_kernel(
    const float* __restrict__ Wo, float* __restrict__ out)
{
    const int m0 = blockIdx.y * 128;
    const int n0 = blockIdx.x * 128;
    float acc[8][8] = {};
    gemm_tile<false>(g_Vals, DIN, Wo, DIN, DIN, m0, n0, acc);

    const int tx = threadIdx.x & 15, ty = threadIdx.x >> 4;
#pragma unroll
    for (int i = 0; i < 8; ++i) {
        const int m = m0 + ty * 8 + i;
#pragma unroll
        for (int j = 0; j < 8; ++j) {
            const int n = n0 + tx * 8 + j;
            out[(size_t)m * DIN + n] = acc[i][j];
        }
    }
}

// ---------------------------------------------------------------------------
extern "C" void kernel_launch(void* const* d_in, const int* in_sizes, int n_in,
                              void* d_out, int out_size)
{
    const float* x  = (const float*)d_in[0];
    const float* wq = (const float*)d_in[1];
    const float* wk = (const float*)d_in[2];
    const float* wv = (const float*)d_in[3];
    const float* wo = (const float*)d_in[4];
    float* out = (float*)d_out;

    proj_kernel<<<dim3(DIN / 128, MALL / 128, 3), 256>>>(x, wq, wk, wv);
    colsum_kernel<<<NH, HD>>>();
    score_kernel<<<dim3(SQ / 128, SQ / 128, NH), 256>>>();
    pv_kernel<<<dim3(1, SQ / 128, NH), 256>>>();
    out_kernel<<<dim3(DIN / 128, MALL / 128, 1), 256>>>(wo, out);
}

// round 2
// speedup vs baseline: 2.0332x; 2.0332x over previous
#include <cuda_runtime.h>
#include <cstdint>

// Problem constants
#define SQ   2048
#define NH   16
#define HD   64
#define DIN  1024
#define MALL 4096

#define BM 128
#define BN 128
#define BK 16
#define AS_STRIDE 20    // [row][k] layout pad (conflict-free frag loads)
#define BS_STRIDE 132   // [k][n]  layout pad (conflict-free frag loads)

// Scratch (device globals; no runtime allocation allowed)
__device__ float g_Qc[NH * SQ * 128];            // [h][s][b*64+d]  (Q0|Q1)
__device__ float g_Kc[NH * SQ * 128];            // [h][s][b*64+d]  (K0|-K1)
__device__ float g_Vc[NH * SQ * 128];            // [h][s][b*64+d]  (V0|V1)
__device__ float g_Attn[(size_t)NH * SQ * SQ];   // [h][q][k] sigmoid probs
__device__ float g_Vals[2 * SQ * DIN];           // [b][s][h*64+d]
__device__ float g_Colsum[NH * HD];

// ---------------------------------------------------------------------------
// helpers
// ---------------------------------------------------------------------------
__device__ __forceinline__ uint32_t f2tf32(float f) {
    uint32_t r;
    asm("cvt.rna.tf32.f32 %0, %1;" : "=r"(r) : "f"(f));
    return r;
}

__device__ __forceinline__ void cp16(void* dst_smem, const void* src) {
    uint32_t d = (uint32_t)__cvta_generic_to_shared(dst_smem);
    asm volatile("cp.async.ca.shared.global [%0], [%1], 16;\n" :: "r"(d), "l"(src));
}

__device__ __forceinline__ void mma_tf32(float c[4], const uint32_t a[4], const uint32_t b[2]) {
    asm volatile(
        "mma.sync.aligned.m16n8k8.row.col.f32.tf32.tf32.f32 "
        "{%0,%1,%2,%3}, {%4,%5,%6,%7}, {%8,%9}, {%0,%1,%2,%3};"
        : "+f"(c[0]), "+f"(c[1]), "+f"(c[2]), "+f"(c[3])
        : "r"(a[0]), "r"(a[1]), "r"(a[2]), "r"(a[3]), "r"(b[0]), "r"(b[1]));
}

// ---------------------------------------------------------------------------
// Core: 128x128 block GEMM on mma.sync tf32.
// BT=false: C = A[MxK] * B[KxN]        (NN, both row-major)
// BT=true : C = A[MxK] * B[NxK]^T      (NT; native for mma row.col)
// X3=true : 3xTF32 (hi*hi + hi*lo + lo*hi) ~= fp32 precision
// 256 threads = 8 warps as 4(m) x 2(n); warp tile 32x64; per-warp 2x8 m16n8 tiles.
// K must be a multiple of 16; tiles fully in-bounds.
// ---------------------------------------------------------------------------
template <bool BT, bool X3>
__device__ __forceinline__ void gemm_mma(
    const float* __restrict__ A, int lda,
    const float* __restrict__ B, int ldb,
    int K, int m0, int n0, float c[2][8][4])
{
    __shared__ float As[2][BM * AS_STRIDE];
    __shared__ float Bs[2][BM * AS_STRIDE];   // NT uses [n][k] stride 20; NN uses [k][n] stride 132 (fits)

    const int tid  = threadIdx.x;
    const int lane = tid & 31;
    const int warp = tid >> 5;
    const int wm   = (warp & 3) * 32;
    const int wn   = (warp >> 2) * 64;

    auto load_stage = [&](int stage, int k0) {
#pragma unroll
        for (int r = 0; r < 2; ++r) {
            int id  = tid + r * 256;
            int row = id >> 2;
            int kv  = (id & 3) << 2;
            cp16(&As[stage][row * AS_STRIDE + kv],
                 A + (size_t)(m0 + row) * lda + k0 + kv);
        }
        if (BT) {
#pragma unroll
            for (int r = 0; r < 2; ++r) {
                int id  = tid + r * 256;
                int row = id >> 2;
                int kv  = (id & 3) << 2;
                cp16(&Bs[stage][row * AS_STRIDE + kv],
                     B + (size_t)(n0 + row) * ldb + k0 + kv);
            }
        } else {
#pragma unroll
            for (int r = 0; r < 2; ++r) {
                int id  = tid + r * 256;
                int row = id >> 5;
                int nv  = (id & 31) << 2;
                cp16(&Bs[stage][row * BS_STRIDE + nv],
                     B + (size_t)(k0 + row) * ldb + n0 + nv);
            }
        }
        asm volatile("cp.async.commit_group;");
    };

    load_stage(0, 0);
    const int nIter = K / BK;

    for (int it = 0; it < nIter; ++it) {
        asm volatile("cp.async.wait_group 0;");
        __syncthreads();
        const int buf = it & 1;
        if (it + 1 < nIter) load_stage(buf ^ 1, (it + 1) * BK);

#pragma unroll
        for (int s = 0; s < 2; ++s) {
            const int ks = s * 8;
            const int kk = ks + (lane & 3);

            uint32_t ahi[2][4], alo[2][4];
#pragma unroll
            for (int mt = 0; mt < 2; ++mt) {
                const int row = wm + mt * 16 + (lane >> 2);
                float a0 = As[buf][row * AS_STRIDE + kk];
                float a1 = As[buf][(row + 8) * AS_STRIDE + kk];
                float a2 = As[buf][row * AS_STRIDE + kk + 4];
                float a3 = As[buf][(row + 8) * AS_STRIDE + kk + 4];
                ahi[mt][0] = f2tf32(a0);
                ahi[mt][1] = f2tf32(a1);
                ahi[mt][2] = f2tf32(a2);
                ahi[mt][3] = f2tf32(a3);
                if (X3) {
                    alo[mt][0] = f2tf32(a0 - __uint_as_float(ahi[mt][0]));
                    alo[mt][1] = f2tf32(a1 - __uint_as_float(ahi[mt][1]));
                    alo[mt][2] = f2tf32(a2 - __uint_as_float(ahi[mt][2]));
                    alo[mt][3] = f2tf32(a3 - __uint_as_float(ahi[mt][3]));
                }
            }

            uint32_t bhi[8][2], blo[8][2];
#pragma unroll
            for (int nt = 0; nt < 8; ++nt) {
                const int col = wn + nt * 8 + (lane >> 2);
                float b0, b1;
                if (BT) {
                    b0 = Bs[buf][col * AS_STRIDE + kk];
                    b1 = Bs[buf][col * AS_STRIDE + kk + 4];
                } else {
                    b0 = Bs[buf][kk * BS_STRIDE + col];
                    b1 = Bs[buf][(kk + 4) * BS_STRIDE + col];
                }
                bhi[nt][0] = f2tf32(b0);
                bhi[nt][1] = f2tf32(b1);
                if (X3) {
                    blo[nt][0] = f2tf32(b0 - __uint_as_float(bhi[nt][0]));
                    blo[nt][1] = f2tf32(b1 - __uint_as_float(bhi[nt][1]));
                }
            }

#pragma unroll
            for (int mt = 0; mt < 2; ++mt)
#pragma unroll
                for (int nt = 0; nt < 8; ++nt) {
                    mma_tf32(c[mt][nt], ahi[mt], bhi[nt]);
                    if (X3) {
                        mma_tf32(c[mt][nt], ahi[mt], blo[nt]);
                        mma_tf32(c[mt][nt], alo[mt], bhi[nt]);
                    }
                }
        }
        __syncthreads();
    }
}

// Fragment -> (m, n) mapping shared by all epilogues:
// m = m0 + wm + mt*16 + lane/4 + p*8 ; n = n0 + wn + nt*8 + (lane%4)*2 (+0/1)

// ---------------------------------------------------------------------------
// 1) Projections (3xTF32 for Q/K; V also via z switch — z=2 uses 1x path below)
// ---------------------------------------------------------------------------
template <bool X3>
__global__ __launch_bounds__(256) void proj_kernel(
    const float* __restrict__ x, const float* __restrict__ W, int z)
{
    float* dst = (z == 0) ? g_Qc : (z == 1) ? g_Kc : g_Vc;

    const int m0 = blockIdx.y * BM;
    const int n0 = blockIdx.x * BN;
    float c[2][8][4] = {};
    gemm_mma<false, X3>(x, DIN, W, DIN, DIN, m0, n0, c);

    const int lane = threadIdx.x & 31, warp = threadIdx.x >> 5;
    const int wm = (warp & 3) * 32, wn = (warp >> 2) * 64;
#pragma unroll
    for (int mt = 0; mt < 2; ++mt)
#pragma unroll
        for (int nt = 0; nt < 8; ++nt)
#pragma unroll
            for (int p = 0; p < 2; ++p) {
                const int m = m0 + wm + mt * 16 + (lane >> 2) + p * 8;
                const int n = n0 + wn + nt * 8 + (lane & 3) * 2;
                const int b = m >> 11, sp = m & 2047;
                const int h = n >> 6,  d  = n & 63;
                float2 v = make_float2(c[mt][nt][2 * p], c[mt][nt][2 * p + 1]);
                if (z == 1 && b == 1) { v.x = -v.x; v.y = -v.y; }
                *(float2*)&dst[(size_t)((h << 11) + sp) * 128 + (b << 6) + d] = v;
            }
}

// ---------------------------------------------------------------------------
__global__ void colsum_kernel()
{
    const int h = blockIdx.x;
    const int d = threadIdx.x;  // 64 threads
    const float* v = g_Vc + (size_t)h * SQ * 128 + 64 + d;
    float s = 0.f;
    for (int k = 0; k < SQ; ++k) s += v[(size_t)k * 128];
    g_Colsum[h * HD + d] = s;
}

// ---------------------------------------------------------------------------
// 2) Scores (NT, K=128, 3xTF32): sigmoid((Qc @ Kc^T)/32)
// ---------------------------------------------------------------------------
__global__ __launch_bounds__(256) void score_kernel()
{
    const int h = blockIdx.z;
    const float* A = g_Qc + (size_t)h * SQ * 128;
    const float* B = g_Kc + (size_t)h * SQ * 128;
    float* C       = g_Attn + (size_t)h * SQ * SQ;

    const int m0 = blockIdx.y * BM;
    const int n0 = blockIdx.x * BN;
    float c[2][8][4] = {};
    gemm_mma<true, true>(A, 128, B, 128, 128, m0, n0, c);

    const int lane = threadIdx.x & 31, warp = threadIdx.x >> 5;
    const int wm = (warp & 3) * 32, wn = (warp >> 2) * 64;
    const float inv_scale = 1.0f / 32.0f;
#pragma unroll
    for (int mt = 0; mt < 2; ++mt)
#pragma unroll
        for (int nt = 0; nt < 8; ++nt)
#pragma unroll
            for (int p = 0; p < 2; ++p) {
                const int m = m0 + wm + mt * 16 + (lane >> 2) + p * 8;
                const int n = n0 + wn + nt * 8 + (lane & 3) * 2;
                float2 v;
                v.x = 1.0f / (1.0f + __expf(-c[mt][nt][2 * p] * inv_scale));
                v.y = 1.0f / (1.0f + __expf(-c[mt][nt][2 * p + 1] * inv_scale));
                *(float2*)&C[(size_t)m * SQ + n] = v;
            }
}

// ---------------------------------------------------------------------------
// 3) PV (NN, N=128, 1xTF32): vals0 = A@V0 ; vals1 = colsum(V1) - A@V1
// ---------------------------------------------------------------------------
__global__ __launch_bounds__(256) void pv_kernel()
{
    const int h = blockIdx.z;
    const float* A = g_Attn + (size_t)h * SQ * SQ;
    const float* B = g_Vc + (size_t)h * SQ * 128;

    const int m0 = blockIdx.y * BM;
    float c[2][8][4] = {};
    gemm_mma<false, false>(A, SQ, B, 128, SQ, m0, 0, c);

    const int lane = threadIdx.x & 31, warp = threadIdx.x >> 5;
    const int wm = (warp & 3) * 32, wn = (warp >> 2) * 64;
#pragma unroll
    for (int mt = 0; mt < 2; ++mt)
#pragma unroll
        for (int nt = 0; nt < 8; ++nt)
#pragma unroll
            for (int p = 0; p < 2; ++p) {
                const int q = m0 + wm + mt * 16 + (lane >> 2) + p * 8;
                const int n = wn + nt * 8 + (lane & 3) * 2;
                float2 v = make_float2(c[mt][nt][2 * p], c[mt][nt][2 * p + 1]);
                if (n < 64) {
                    *(float2*)&g_Vals[(size_t)q * DIN + h * 64 + n] = v;
                } else {
                    const int d = n - 64;
                    float2 cs = *(const float2*)&g_Colsum[h * HD + d];
                    v.x = cs.x - v.x;
                    v.y = cs.y - v.y;
                    *(float2*)&g_Vals[(size_t)(SQ + q) * DIN + h * 64 + d] = v;
                }
            }
}

// ---------------------------------------------------------------------------
// 4) Output projection (NN, 1xTF32): out = Vals @ W_o
// ---------------------------------------------------------------------------
__global__ __launch_bounds__(256) void out_kernel(
    const float* __restrict__ Wo, float* __restrict__ out)
{
    const int m0 = blockIdx.y * BM;
    const int n0 = blockIdx.x * BN;
    float c[2][8][4] = {};
    gemm_mma<false, false>(g_Vals, DIN, Wo, DIN, DIN, m0, n0, c);

    const int lane = threadIdx.x & 31, warp = threadIdx.x >> 5;
    const int wm = (warp & 3) * 32, wn = (warp >> 2) * 64;
#pragma unroll
    for (int mt = 0; mt < 2; ++mt)
#pragma unroll
        for (int nt = 0; nt < 8; ++nt)
#pragma unroll
            for (int p = 0; p < 2; ++p) {
                const int m = m0 + wm + mt * 16 + (lane >> 2) + p * 8;
                const int n = n0 + wn + nt * 8 + (lane & 3) * 2;
                *(float2*)&out[(size_t)m * DIN + n] =
                    make_float2(c[mt][nt][2 * p], c[mt][nt][2 * p + 1]);
            }
}

// ---------------------------------------------------------------------------
extern "C" void kernel_launch(void* const* d_in, const int* in_sizes, int n_in,
                              void* d_out, int out_size)
{
    const float* x  = (const float*)d_in[0];
    const float* wq = (const float*)d_in[1];
    const float* wk = (const float*)d_in[2];
    const float* wv = (const float*)d_in[3];
    const float* wo = (const float*)d_in[4];
    float* out = (float*)d_out;

    dim3 gproj(DIN / BN, MALL / BM, 1);
    proj_kernel<true ><<<gproj, 256>>>(x, wq, 0);   // Q : 3xTF32
    proj_kernel<true ><<<gproj, 256>>>(x, wk, 1);   // K : 3xTF32
    proj_kernel<false><<<gproj, 256>>>(x, wv, 2);   // V : 1xTF32
    colsum_kernel<<<NH, HD>>>();
    score_kernel<<<dim3(SQ / BN, SQ / BM, NH), 256>>>();
    pv_kernel<<<dim3(1, SQ / BM, NH), 256>>>();
    out_kernel<<<dim3(DIN / BN, MALL / BM, 1), 256>>>(wo, out);
}

// round 3
// speedup vs baseline: 2.0336x; 1.0002x over previous
#include <cuda_runtime.h>
#include <cstdint>

// Problem constants
#define SQ   2048
#define NH   16
#define HD   64
#define DIN  1024
#define MALL 4096

#define BM 128
#define BN 128
#define BK 16
#define AS_STRIDE 20    // [row][k] layout pad (conflict-free frag loads)
#define BS_STRIDE 132   // [k][n]  layout pad (conflict-free frag loads)

// Scratch (device globals; no runtime allocation allowed)
__device__ float g_Qc[NH * SQ * 128];            // [h][s][b*64+d]  (Q0|Q1)
__device__ float g_Kc[NH * SQ * 128];            // [h][s][b*64+d]  (K0|-K1)
__device__ float g_Vc[NH * SQ * 128];            // [h][s][b*64+d]  (V0|V1)
__device__ float g_Attn[(size_t)NH * SQ * SQ];   // [h][q][k] sigmoid probs
__device__ float g_Vals[2 * SQ * DIN];           // [b][s][h*64+d]
__device__ float g_Colsum[NH * HD];

// ---------------------------------------------------------------------------
// helpers
// ---------------------------------------------------------------------------
__device__ __forceinline__ uint32_t f2tf32(float f) {
    uint32_t r;
    asm("cvt.rna.tf32.f32 %0, %1;" : "=r"(r) : "f"(f));
    return r;
}

__device__ __forceinline__ void cp16(void* dst_smem, const void* src) {
    uint32_t d = (uint32_t)__cvta_generic_to_shared(dst_smem);
    asm volatile("cp.async.ca.shared.global [%0], [%1], 16;\n" :: "r"(d), "l"(src));
}

__device__ __forceinline__ void mma_tf32(float c[4], const uint32_t a[4], const uint32_t b[2]) {
    asm volatile(
        "mma.sync.aligned.m16n8k8.row.col.f32.tf32.tf32.f32 "
        "{%0,%1,%2,%3}, {%4,%5,%6,%7}, {%8,%9}, {%0,%1,%2,%3};"
        : "+f"(c[0]), "+f"(c[1]), "+f"(c[2]), "+f"(c[3])
        : "r"(a[0]), "r"(a[1]), "r"(a[2]), "r"(a[3]), "r"(b[0]), "r"(b[1]));
}

// ---------------------------------------------------------------------------
// Core: 128x128 block GEMM on mma.sync tf32.
// BT=false: C = A[MxK] * B[KxN]        (NN, both row-major)
// BT=true : C = A[MxK] * B[NxK]^T      (NT; native for mma row.col)
// X3=true : 3xTF32 (hi*hi + hi*lo + lo*hi) ~= fp32 precision
// 256 threads = 8 warps as 4(m) x 2(n); warp tile 32x64; per-warp 2x8 m16n8 tiles.
// K must be a multiple of 16; tiles fully in-bounds.
// ---------------------------------------------------------------------------
template <bool BT, bool X3>
__device__ __forceinline__ void gemm_mma(
    const float* __restrict__ A, int lda,
    const float* __restrict__ B, int ldb,
    int K, int m0, int n0, float c[2][8][4])
{
    __shared__ float As[2][BM * AS_STRIDE];
    __shared__ float Bs[2][BM * AS_STRIDE];   // NT uses [n][k] stride 20; NN uses [k][n] stride 132 (fits)

    const int tid  = threadIdx.x;
    const int lane = tid & 31;
    const int warp = tid >> 5;
    const int wm   = (warp & 3) * 32;
    const int wn   = (warp >> 2) * 64;

    auto load_stage = [&](int stage, int k0) {
#pragma unroll
        for (int r = 0; r < 2; ++r) {
            int id  = tid + r * 256;
            int row = id >> 2;
            int kv  = (id & 3) << 2;
            cp16(&As[stage][row * AS_STRIDE + kv],
                 A + (size_t)(m0 + row) * lda + k0 + kv);
        }
        if (BT) {
#pragma unroll
            for (int r = 0; r < 2; ++r) {
                int id  = tid + r * 256;
                int row = id >> 2;
                int kv  = (id & 3) << 2;
                cp16(&Bs[stage][row * AS_STRIDE + kv],
                     B + (size_t)(n0 + row) * ldb + k0 + kv);
            }
        } else {
#pragma unroll
            for (int r = 0; r < 2; ++r) {
                int id  = tid + r * 256;
                int row = id >> 5;
                int nv  = (id & 31) << 2;
                cp16(&Bs[stage][row * BS_STRIDE + nv],
                     B + (size_t)(k0 + row) * ldb + n0 + nv);
            }
        }
        asm volatile("cp.async.commit_group;");
    };

    load_stage(0, 0);
    const int nIter = K / BK;

    for (int it = 0; it < nIter; ++it) {
        asm volatile("cp.async.wait_group 0;");
        __syncthreads();
        const int buf = it & 1;
        if (it + 1 < nIter) load_stage(buf ^ 1, (it + 1) * BK);

#pragma unroll
        for (int s = 0; s < 2; ++s) {
            const int ks = s * 8;
            const int kk = ks + (lane & 3);

            uint32_t ahi[2][4], alo[2][4];
#pragma unroll
            for (int mt = 0; mt < 2; ++mt) {
                const int row = wm + mt * 16 + (lane >> 2);
                float a0 = As[buf][row * AS_STRIDE + kk];
                float a1 = As[buf][(row + 8) * AS_STRIDE + kk];
                float a2 = As[buf][row * AS_STRIDE + kk + 4];
                float a3 = As[buf][(row + 8) * AS_STRIDE + kk + 4];
                ahi[mt][0] = f2tf32(a0);
                ahi[mt][1] = f2tf32(a1);
                ahi[mt][2] = f2tf32(a2);
                ahi[mt][3] = f2tf32(a3);
                if (X3) {
                    alo[mt][0] = f2tf32(a0 - __uint_as_float(ahi[mt][0]));
                    alo[mt][1] = f2tf32(a1 - __uint_as_float(ahi[mt][1]));
                    alo[mt][2] = f2tf32(a2 - __uint_as_float(ahi[mt][2]));
                    alo[mt][3] = f2tf32(a3 - __uint_as_float(ahi[mt][3]));
                }
            }

            uint32_t bhi[8][2], blo[8][2];
#pragma unroll
            for (int nt = 0; nt < 8; ++nt) {
                const int col = wn + nt * 8 + (lane >> 2);
                float b0, b1;
                if (BT) {
                    b0 = Bs[buf][col * AS_STRIDE + kk];
                    b1 = Bs[buf][col * AS_STRIDE + kk + 4];
                } else {
                    b0 = Bs[buf][kk * BS_STRIDE + col];
                    b1 = Bs[buf][(kk + 4) * BS_STRIDE + col];
                }
                bhi[nt][0] = f2tf32(b0);
                bhi[nt][1] = f2tf32(b1);
                if (X3) {
                    blo[nt][0] = f2tf32(b0 - __uint_as_float(bhi[nt][0]));
                    blo[nt][1] = f2tf32(b1 - __uint_as_float(bhi[nt][1]));
                }
            }

#pragma unroll
            for (int mt = 0; mt < 2; ++mt)
#pragma unroll
                for (int nt = 0; nt < 8; ++nt) {
                    mma_tf32(c[mt][nt], ahi[mt], bhi[nt]);
                    if (X3) {
                        mma_tf32(c[mt][nt], ahi[mt], blo[nt]);
                        mma_tf32(c[mt][nt], alo[mt], bhi[nt]);
                    }
                }
        }
        __syncthreads();
    }
}

// Fragment -> (m, n) mapping shared by all epilogues:
// m = m0 + wm + mt*16 + lane/4 + p*8 ; n = n0 + wn + nt*8 + (lane%4)*2 (+0/1)

// ---------------------------------------------------------------------------
// 1) Projections (3xTF32 for Q/K; V also via z switch — z=2 uses 1x path below)
// ---------------------------------------------------------------------------
template <bool X3>
__global__ __launch_bounds__(256) void proj_kernel(
    const float* __restrict__ x, const float* __restrict__ W, int z)
{
    float* dst = (z == 0) ? g_Qc : (z == 1) ? g_Kc : g_Vc;

    const int m0 = blockIdx.y * BM;
    const int n0 = blockIdx.x * BN;
    float c[2][8][4] = {};
    gemm_mma<false, X3>(x, DIN, W, DIN, DIN, m0, n0, c);

    const int lane = threadIdx.x & 31, warp = threadIdx.x >> 5;
    const int wm = (warp & 3) * 32, wn = (warp >> 2) * 64;
#pragma unroll
    for (int mt = 0; mt < 2; ++mt)
#pragma unroll
        for (int nt = 0; nt < 8; ++nt)
#pragma unroll
            for (int p = 0; p < 2; ++p) {
                const int m = m0 + wm + mt * 16 + (lane >> 2) + p * 8;
                const int n = n0 + wn + nt * 8 + (lane & 3) * 2;
                const int b = m >> 11, sp = m & 2047;
                const int h = n >> 6,  d  = n & 63;
                float2 v = make_float2(c[mt][nt][2 * p], c[mt][nt][2 * p + 1]);
                if (z == 1 && b == 1) { v.x = -v.x; v.y = -v.y; }
                *(float2*)&dst[(size_t)((h << 11) + sp) * 128 + (b << 6) + d] = v;
            }
}

// ---------------------------------------------------------------------------
__global__ void colsum_kernel()
{
    const int h = blockIdx.x;
    const int d = threadIdx.x;  // 64 threads
    const float* v = g_Vc + (size_t)h * SQ * 128 + 64 + d;
    float s = 0.f;
    for (int k = 0; k < SQ; ++k) s += v[(size_t)k * 128];
    g_Colsum[h * HD + d] = s;
}

// ---------------------------------------------------------------------------
// 2) Scores (NT, K=128, 3xTF32): sigmoid((Qc @ Kc^T)/32)
// ---------------------------------------------------------------------------
__global__ __launch_bounds__(256) void score_kernel()
{
    const int h = blockIdx.z;
    const float* A = g_Qc + (size_t)h * SQ * 128;
    const float* B = g_Kc + (size_t)h * SQ * 128;
    float* C       = g_Attn + (size_t)h * SQ * SQ;

    const int m0 = blockIdx.y * BM;
    const int n0 = blockIdx.x * BN;
    float c[2][8][4] = {};
    gemm_mma<true, true>(A, 128, B, 128, 128, m0, n0, c);

    const int lane = threadIdx.x & 31, warp = threadIdx.x >> 5;
    const int wm = (warp & 3) * 32, wn = (warp >> 2) * 64;
    const float inv_scale = 1.0f / 32.0f;
#pragma unroll
    for (int mt = 0; mt < 2; ++mt)
#pragma unroll
        for (int nt = 0; nt < 8; ++nt)
#pragma unroll
            for (int p = 0; p < 2; ++p) {
                const int m = m0 + wm + mt * 16 + (lane >> 2) + p * 8;
                const int n = n0 + wn + nt * 8 + (lane & 3) * 2;
                float2 v;
                v.x = 1.0f / (1.0f + __expf(-c[mt][nt][2 * p] * inv_scale));
                v.y = 1.0f / (1.0f + __expf(-c[mt][nt][2 * p + 1] * inv_scale));
                *(float2*)&C[(size_t)m * SQ + n] = v;
            }
}

// ---------------------------------------------------------------------------
// 3) PV (NN, N=128, 1xTF32): vals0 = A@V0 ; vals1 = colsum(V1) - A@V1
// ---------------------------------------------------------------------------
__global__ __launch_bounds__(256) void pv_kernel()
{
    const int h = blockIdx.z;
    const float* A = g_Attn + (size_t)h * SQ * SQ;
    const float* B = g_Vc + (size_t)h * SQ * 128;

    const int m0 = blockIdx.y * BM;
    float c[2][8][4] = {};
    gemm_mma<false, false>(A, SQ, B, 128, SQ, m0, 0, c);

    const int lane = threadIdx.x & 31, warp = threadIdx.x >> 5;
    const int wm = (warp & 3) * 32, wn = (warp >> 2) * 64;
#pragma unroll
    for (int mt = 0; mt < 2; ++mt)
#pragma unroll
        for (int nt = 0; nt < 8; ++nt)
#pragma unroll
            for (int p = 0; p < 2; ++p) {
                const int q = m0 + wm + mt * 16 + (lane >> 2) + p * 8;
                const int n = wn + nt * 8 + (lane & 3) * 2;
                float2 v = make_float2(c[mt][nt][2 * p], c[mt][nt][2 * p + 1]);
                if (n < 64) {
                    *(float2*)&g_Vals[(size_t)q * DIN + h * 64 + n] = v;
                } else {
                    const int d = n - 64;
                    float2 cs = *(const float2*)&g_Colsum[h * HD + d];
                    v.x = cs.x - v.x;
                    v.y = cs.y - v.y;
                    *(float2*)&g_Vals[(size_t)(SQ + q) * DIN + h * 64 + d] = v;
                }
            }
}

// ---------------------------------------------------------------------------
// 4) Output projection (NN, 1xTF32): out = Vals @ W_o
// ---------------------------------------------------------------------------
__global__ __launch_bounds__(256) void out_kernel(
    const float* __restrict__ Wo, float* __restrict__ out)
{
    const int m0 = blockIdx.y * BM;
    const int n0 = blockIdx.x * BN;
    float c[2][8][4] = {};
    gemm_mma<false, false>(g_Vals, DIN, Wo, DIN, DIN, m0, n0, c);

    const int lane = threadIdx.x & 31, warp = threadIdx.x >> 5;
    const int wm = (warp & 3) * 32, wn = (warp >> 2) * 64;
#pragma unroll
    for (int mt = 0; mt < 2; ++mt)
#pragma unroll
        for (int nt = 0; nt < 8; ++nt)
#pragma unroll
            for (int p = 0; p < 2; ++p) {
                const int m = m0 + wm + mt * 16 + (lane >> 2) + p * 8;
                const int n = n0 + wn + nt * 8 + (lane & 3) * 2;
                *(float2*)&out[(size_t)m * DIN + n] =
                    make_float2(c[mt][nt][2 * p], c[mt][nt][2 * p + 1]);
            }
}

// ---------------------------------------------------------------------------
extern "C" void kernel_launch(void* const* d_in, const int* in_sizes, int n_in,
                              void* d_out, int out_size)
{
    const float* x  = (const float*)d_in[0];
    const float* wq = (const float*)d_in[1];
    const float* wk = (const float*)d_in[2];
    const float* wv = (const float*)d_in[3];
    const float* wo = (const float*)d_in[4];
    float* out = (float*)d_out;

    dim3 gproj(DIN / BN, MALL / BM, 1);
    proj_kernel<true ><<<gproj, 256>>>(x, wq, 0);   // Q : 3xTF32
    proj_kernel<true ><<<gproj, 256>>>(x, wk, 1);   // K : 3xTF32
    proj_kernel<false><<<gproj, 256>>>(x, wv, 2);   // V : 1xTF32
    colsum_kernel<<<NH, HD>>>();
    score_kernel<<<dim3(SQ / BN, SQ / BM, NH), 256>>>();
    pv_kernel<<<dim3(1, SQ / BM, NH), 256>>>();
    out_kernel<<<dim3(DIN / BN, MALL / BM, 1), 256>>>(wo, out);
}

// round 5
// speedup vs baseline: 2.2920x; 1.1271x over previous
#include <cuda_runtime.h>
#include <cuda_fp16.h>
#include <cstdint>

// ---------------------------------------------------------------------------
// B=2,S=2048,D=1024,H=16,HD=64, scale=32. softmax over batch (B=2) ==
//   P     = sigmoid((Q0K0^T - Q1K1^T)/32)   per head [2048x2048]
//   vals0 = P @ V0 ;  vals1 = colsum(V1) - P @ V1
// All GEMMs: fp16 mma.sync m16n8k16, NT form, hi/lo split operands.
// ---------------------------------------------------------------------------

__device__ __align__(128) __half g_xhi[4096 * 1024];
__device__ __align__(128) __half g_xlo[4096 * 1024];
__device__ __align__(128) __half g_wThi[4 * 1024 * 1024];   // [z][n][k]
__device__ __align__(128) __half g_wTlo[4 * 1024 * 1024];
__device__ __align__(128) __half g_Qhi[16 * 2048 * 128];    // [h][s][b*64+d]
__device__ __align__(128) __half g_Qlo[16 * 2048 * 128];
__device__ __align__(128) __half g_Khi[16 * 2048 * 128];    // K1 negated
__device__ __align__(128) __half g_Klo[16 * 2048 * 128];
__device__ __align__(128) float  g_Vf [16 * 2048 * 128];    // fp32 V [h][s][b*64+d]
__device__ __align__(128) __half g_Vthi[16 * 128 * 2048];   // [h][b*64+d][s]
__device__ __align__(128) __half g_Vtlo[16 * 128 * 2048];
__device__ __align__(128) __half g_P[(size_t)16 * 2048 * 2048];
__device__ __align__(128) __half g_Valshi[4096 * 1024];     // [b*2048+q][h*64+d]
__device__ __align__(128) __half g_Valslo[4096 * 1024];
__device__ float g_ColPart[16 * 16 * 64];
__device__ float g_Colsum[16 * 64];

#define SSTR  24                 // halfs per smem row (16 data + 8 pad)
#define PLANE (128 * SSTR)       // halfs per tile plane (6144 B)

// ---------------------------------------------------------------------------
static __device__ __forceinline__ void cpa16(const __half* dst_smem, const void* src) {
    uint32_t d = (uint32_t)__cvta_generic_to_shared(dst_smem);
    asm volatile("cp.async.cg.shared.global [%0], [%1], 16;" :: "r"(d), "l"(src));
}
static __device__ __forceinline__ uint32_t lds32(const __half* p) {
    return *reinterpret_cast<const uint32_t*>(p);
}
static __device__ __forceinline__ void mma16816(float c[4], const uint32_t a[4],
                                                uint32_t b0, uint32_t b1) {
    asm volatile(
        "mma.sync.aligned.m16n8k16.row.col.f32.f16.f16.f32 "
        "{%0,%1,%2,%3}, {%4,%5,%6,%7}, {%8,%9}, {%0,%1,%2,%3};"
        : "+f"(c[0]), "+f"(c[1]), "+f"(c[2]), "+f"(c[3])
        : "r"(a[0]), "r"(a[1]), "r"(a[2]), "r"(a[3]), "r"(b0), "r"(b1));
}
static __device__ __forceinline__ void splitstore(__half* hp, __half* lp,
                                                  float v0, float v1) {
    __half h0 = __float2half_rn(v0), h1 = __float2half_rn(v1);
    *(__half2*)hp = __halves2half2(h0, h1);
    *(__half2*)lp = __halves2half2(__float2half_rn(v0 - __half2float(h0)),
                                   __float2half_rn(v1 - __half2float(h1)));
}

enum { EPI_PROJ = 0, EPI_SCORE, EPI_PV, EPI_OUT };

// ---------------------------------------------------------------------------
// 128x128-tile NT GEMM, fp16 mma, fused epilogue.
// NTERM=3: Ahi*Bhi + Ahi*Blo + Alo*Bhi   (A planes: hi,lo)
// NTERM=2: A*Bhi + A*Blo                 (A plane: single)
// 256 thr = 8 warps (4m x 2n); warp 32x64; per warp 2x8 m16n8k16 tiles.
// ---------------------------------------------------------------------------
template <int KTOT, int NTERM, int EPI>
__global__ __launch_bounds__(256) void gemm_kernel(float* outp)
{
    extern __shared__ __half sm[];
    const int NA  = (NTERM == 3) ? 2 : 1;
    const int NPL = NA + 2;

    const int tid = threadIdx.x, warp = tid >> 5, lane = tid & 31;
    const int wm = (warp & 3) * 32, wn = (warp >> 2) * 64;
    const int m0 = blockIdx.y * 128, n0 = blockIdx.x * 128, z = blockIdx.z;

    const __half *Ahi, *Alo = nullptr, *Bhi, *Blo;
    int lda, ldb;
    if (EPI == EPI_PROJ) {
        Ahi = g_xhi; Alo = g_xlo; lda = 1024;
        Bhi = g_wThi + (size_t)z * 1048576; Blo = g_wTlo + (size_t)z * 1048576; ldb = 1024;
    } else if (EPI == EPI_SCORE) {
        Ahi = g_Qhi + (size_t)z * 2048 * 128; Alo = g_Qlo + (size_t)z * 2048 * 128; lda = 128;
        Bhi = g_Khi + (size_t)z * 2048 * 128; Blo = g_Klo + (size_t)z * 2048 * 128; ldb = 128;
    } else if (EPI == EPI_PV) {
        Ahi = g_P + (size_t)z * 2048 * 2048; lda = 2048;
        Bhi = g_Vthi + (size_t)z * 128 * 2048; Blo = g_Vtlo + (size_t)z * 128 * 2048; ldb = 2048;
    } else {
        Ahi = g_Valshi; Alo = g_Valslo; lda = 1024;
        Bhi = g_wThi + (size_t)3 * 1048576; Blo = g_wTlo + (size_t)3 * 1048576; ldb = 1024;
    }

    // stage/plane addressing
    auto plane = [&](int st, int pl) { return sm + (st * NPL + pl) * PLANE; };

    const int lrow = tid >> 1, lkh = (tid & 1) * 8;   // 16B per thread per plane
    auto load_stage = [&](int st, int k0) {
        cpa16(plane(st, 0) + lrow * SSTR + lkh,
              Ahi + (size_t)(m0 + lrow) * lda + k0 + lkh);
        if (NA == 2)
            cpa16(plane(st, 1) + lrow * SSTR + lkh,
                  Alo + (size_t)(m0 + lrow) * lda + k0 + lkh);
        cpa16(plane(st, NA + 0) + lrow * SSTR + lkh,
              Bhi + (size_t)(n0 + lrow) * ldb + k0 + lkh);
        cpa16(plane(st, NA + 1) + lrow * SSTR + lkh,
              Blo + (size_t)(n0 + lrow) * ldb + k0 + lkh);
        asm volatile("cp.async.commit_group;" ::: "memory");
    };

    float c[2][8][4] = {};
    const int nCh = KTOT / 16;
    load_stage(0, 0);

    const int kk = (lane & 3) * 2;
    for (int it = 0; it < nCh; ++it) {
        asm volatile("cp.async.wait_group 0;" ::: "memory");
        __syncthreads();
        const int buf = it & 1;
        if (it + 1 < nCh) load_stage(buf ^ 1, (it + 1) * 16);

        // A fragments for all planes
        uint32_t af[2][2][4];
#pragma unroll
        for (int pa = 0; pa < NA; ++pa)
#pragma unroll
            for (int mt = 0; mt < 2; ++mt) {
                const __half* Ap = plane(buf, pa) + (wm + mt * 16 + (lane >> 2)) * SSTR;
                af[pa][mt][0] = lds32(Ap + kk);
                af[pa][mt][1] = lds32(Ap + 8 * SSTR + kk);
                af[pa][mt][2] = lds32(Ap + kk + 8);
                af[pa][mt][3] = lds32(Ap + 8 * SSTR + kk + 8);
            }
        const __half* B0 = plane(buf, NA + 0);
        const __half* B1 = plane(buf, NA + 1);
#pragma unroll
        for (int nt = 0; nt < 8; ++nt) {
            const int co = (wn + nt * 8 + (lane >> 2)) * SSTR;
            uint32_t b00 = lds32(B0 + co + kk), b01 = lds32(B0 + co + kk + 8);
            uint32_t b10 = lds32(B1 + co + kk), b11 = lds32(B1 + co + kk + 8);
#pragma unroll
            for (int mt = 0; mt < 2; ++mt) {
                mma16816(c[mt][nt], af[0][mt], b00, b01);
                mma16816(c[mt][nt], af[0][mt], b10, b11);
                if (NTERM == 3) mma16816(c[mt][nt], af[1][mt], b00, b01);
            }
        }
        __syncthreads();
    }

    // ---- epilogue: m = m0+wm+mt*16+lane/4+p*8 ; n = n0+wn+nt*8+(lane%4)*2 ----
#pragma unroll
    for (int mt = 0; mt < 2; ++mt)
#pragma unroll
        for (int nt = 0; nt < 8; ++nt)
#pragma unroll
            for (int p = 0; p < 2; ++p) {
                const int m = m0 + wm + mt * 16 + (lane >> 2) + p * 8;
                const int nl = wn + nt * 8 + (lane & 3) * 2;
                float v0 = c[mt][nt][2 * p], v1 = c[mt][nt][2 * p + 1];

                if (EPI == EPI_PROJ) {
                    const int b = m >> 11, s = m & 2047;
                    const int n = n0 + nl, h = n >> 6, d = n & 63;
                    const size_t base = ((size_t)(h * 2048 + s)) * 128 + b * 64 + d;
                    if (z == 2) {
                        *(float2*)&g_Vf[base] = make_float2(v0, v1);
                    } else {
                        if (z == 1 && b == 1) { v0 = -v0; v1 = -v1; }
                        __half* Dh = (z == 0) ? g_Qhi : g_Khi;
                        __half* Dl = (z == 0) ? g_Qlo : g_Klo;
                        splitstore(&Dh[base], &Dl[base], v0, v1);
                    }
                } else if (EPI == EPI_SCORE) {
                    float p0 = 1.f / (1.f + __expf(-v0 * 0.03125f));
                    float p1 = 1.f / (1.f + __expf(-v1 * 0.03125f));
                    *(__half2*)&g_P[((size_t)z * 2048 + m) * 2048 + n0 + nl] =
                        __halves2half2(__float2half_rn(p0), __float2half_rn(p1));
                } else if (EPI == EPI_PV) {
                    const int b = nl >> 6, d = nl & 63;
                    if (b) {
                        v0 = g_Colsum[z * 64 + d]     - v0;
                        v1 = g_Colsum[z * 64 + d + 1] - v1;
                    }
                    const size_t base = ((size_t)(b * 2048 + m)) * 1024 + z * 64 + d;
                    splitstore(&g_Valshi[base], &g_Valslo[base], v0, v1);
                } else {
                    *(float2*)&outp[(size_t)m * 1024 + n0 + nl] = make_float2(v0, v1);
                }
            }
}

// ---------------------------------------------------------------------------
// prep kernels
// ---------------------------------------------------------------------------
__global__ __launch_bounds__(256) void split_x_kernel(const float* __restrict__ x)
{
    const size_t i = ((size_t)blockIdx.x * 256 + threadIdx.x) * 4;
    float4 v = *(const float4*)(x + i);
    splitstore(&g_xhi[i],     &g_xlo[i],     v.x, v.y);
    splitstore(&g_xhi[i + 2], &g_xlo[i + 2], v.z, v.w);
}

__global__ __launch_bounds__(256) void trw_kernel(
    const float* __restrict__ w0, const float* __restrict__ w1,
    const float* __restrict__ w2, const float* __restrict__ w3)
{
    const float* W = (blockIdx.z == 0) ? w0 : (blockIdx.z == 1) ? w1
                     : (blockIdx.z == 2) ? w2 : w3;
    __shared__ float t[32][33];
    const int bx = blockIdx.x * 32, by = blockIdx.y * 32;
    const int tx = threadIdx.x & 31, ty8 = threadIdx.x >> 5;
#pragma unroll
    for (int s = 0; s < 4; ++s)
        t[ty8 + s * 8][tx] = W[(size_t)(by + ty8 + s * 8) * 1024 + bx + tx];
    __syncthreads();
    __half* Dh = g_wThi + (size_t)blockIdx.z * 1048576;
    __half* Dl = g_wTlo + (size_t)blockIdx.z * 1048576;
#pragma unroll
    for (int s = 0; s < 4; ++s) {
        const int ty = ty8 + s * 8;
        const float v = t[tx][ty];
        const size_t o = (size_t)(bx + ty) * 1024 + by + tx;
        __half h = __float2half_rn(v);
        Dh[o] = h;
        Dl[o] = __float2half_rn(v - __half2float(h));
    }
}

// transpose V per (head, 128-s-chunk) + deterministic colsum partials of V1
__global__ __launch_bounds__(256) void trv_kernel()
{
    extern __shared__ float tl[];   // [128][129]
    const int sc = blockIdx.x, h = blockIdx.y;
    const int s0 = sc * 128;
    const float* V = g_Vf + ((size_t)h * 2048 + s0) * 128;

    for (int i = threadIdx.x; i < 128 * 128; i += 256)
        tl[(i >> 7) * 129 + (i & 127)] = V[i];
    __syncthreads();

    if (threadIdx.x < 64) {
        float acc = 0.f;
        for (int s = 0; s < 128; ++s) acc += tl[s * 129 + 64 + threadIdx.x];
        g_ColPart[((size_t)h * 16 + sc) * 64 + threadIdx.x] = acc;
    }

    const int dp = threadIdx.x & 127, seg = threadIdx.x >> 7;
    __half* Th = g_Vthi + ((size_t)h * 128 + dp) * 2048 + s0 + seg * 64;
    __half* Tl = g_Vtlo + ((size_t)h * 128 + dp) * 2048 + s0 + seg * 64;
#pragma unroll 8
    for (int j = 0; j < 64; ++j) {
        const float v = tl[(seg * 64 + j) * 129 + dp];
        __half hv = __float2half_rn(v);
        Th[j] = hv;
        Tl[j] = __float2half_rn(v - __half2float(hv));
    }
}

__global__ void redc_kernel()
{
    const int t = threadIdx.x;   // 1024 = 16h * 64d
    const int h = t >> 6, d = t & 63;
    float a = 0.f;
    for (int sc = 0; sc < 16; ++sc)
        a += g_ColPart[((size_t)h * 16 + sc) * 64 + d];
    g_Colsum[t] = a;
}

// ---------------------------------------------------------------------------
extern "C" void kernel_launch(void* const* d_in, const int* in_sizes, int n_in,
                              void* d_out, int out_size)
{
    const float* x  = (const float*)d_in[0];
    const float* wq = (const float*)d_in[1];
    const float* wk = (const float*)d_in[2];
    const float* wv = (const float*)d_in[3];
    const float* wo = (const float*)d_in[4];
    float* out = (float*)d_out;

    const int SM3 = 2 * 4 * PLANE * 2;   // 49152 B (3-term: 4 planes x 2 stages)
    const int SM2 = 2 * 3 * PLANE * 2;   // 36864 B (2-term)
    const int SMT = 128 * 129 * 4;       // 66048 B (transpose tile)

    cudaFuncSetAttribute(gemm_kernel<1024, 3, EPI_PROJ>,  cudaFuncAttributeMaxDynamicSharedMemorySize, SM3);
    cudaFuncSetAttribute(gemm_kernel<128,  3, EPI_SCORE>, cudaFuncAttributeMaxDynamicSharedMemorySize, SM3);
    cudaFuncSetAttribute(gemm_kernel<2048, 2, EPI_PV>,    cudaFuncAttributeMaxDynamicSharedMemorySize, SM2);
    cudaFuncSetAttribute(gemm_kernel<1024, 3, EPI_OUT>,   cudaFuncAttributeMaxDynamicSharedMemorySize, SM3);
    cudaFuncSetAttribute(trv_kernel,                      cudaFuncAttributeMaxDynamicSharedMemorySize, SMT);

    split_x_kernel<<<4096, 256>>>(x);
    trw_kernel<<<dim3(32, 32, 4), 256>>>(wq, wk, wv, wo);

    gemm_kernel<1024, 3, EPI_PROJ><<<dim3(8, 32, 3), 256, SM3>>>(nullptr);

    trv_kernel<<<dim3(16, 16), 256, SMT>>>();
    redc_kernel<<<1, 1024>>>();

    gemm_kernel<128,  3, EPI_SCORE><<<dim3(16, 16, 16), 256, SM3>>>(nullptr);
    gemm_kernel<2048, 2, EPI_PV><<<dim3(1, 16, 16), 256, SM2>>>(nullptr);
    gemm_kernel<1024, 3, EPI_OUT><<<dim3(8, 32, 1), 256, SM3>>>(out);
}

// round 6
// speedup vs baseline: 2.4912x; 1.0869x over previous
#include <cuda_runtime.h>
#include <cuda_fp16.h>
#include <cstdint>

// ---------------------------------------------------------------------------
// B=2,S=2048,D=1024,H=16,HD=64, scale=32. softmax over batch (B=2) ==
//   P     = sigmoid((Q0K0^T - Q1K1^T)/32)   per head [2048x2048]
//   vals0 = P @ V0 ;  vals1 = colsum(V1) - P @ V1
// fp16 mma.sync m16n8k16 NT GEMMs; hi/lo split where precision requires:
//   Q/K proj, score: 3-term   | V proj, out: 2-term | PV: 1-term
// ---------------------------------------------------------------------------

__device__ __align__(128) __half g_xhi[4096 * 1024];
__device__ __align__(128) __half g_xlo[4096 * 1024];
__device__ __align__(128) __half g_wThi[4 * 1024 * 1024];   // [z][n][k]
__device__ __align__(128) __half g_wTlo[4 * 1024 * 1024];
__device__ __align__(128) __half g_Qhi[16 * 2048 * 128];    // [h][s][b*64+d]
__device__ __align__(128) __half g_Qlo[16 * 2048 * 128];
__device__ __align__(128) __half g_Khi[16 * 2048 * 128];    // K1 negated
__device__ __align__(128) __half g_Klo[16 * 2048 * 128];
__device__ __align__(128) float  g_Vf [16 * 2048 * 128];    // fp32 V [h][s][b*64+d]
__device__ __align__(128) __half g_Vthi[16 * 128 * 2048];   // [h][b*64+d][s]
__device__ __align__(128) __half g_P[(size_t)16 * 2048 * 2048];
__device__ __align__(128) __half g_Valshi[4096 * 1024];     // [b*2048+q][h*64+d]
__device__ float g_ColPart[16 * 16 * 64];
__device__ float g_Colsum[16 * 64];

#define SSTR   40                 // halfs per smem row (32 data + 8 pad)
#define PLANEH (128 * SSTR)       // halfs per plane (10240 B)

// ---------------------------------------------------------------------------
static __device__ __forceinline__ void cpa16(const __half* dst_smem, const void* src) {
    uint32_t d = (uint32_t)__cvta_generic_to_shared(dst_smem);
    asm volatile("cp.async.cg.shared.global [%0], [%1], 16;" :: "r"(d), "l"(src));
}
static __device__ __forceinline__ void ldm4(uint32_t r[4], const __half* p) {
    uint32_t a = (uint32_t)__cvta_generic_to_shared(p);
    asm volatile("ldmatrix.sync.aligned.m8n8.x4.shared.b16 {%0,%1,%2,%3}, [%4];"
                 : "=r"(r[0]), "=r"(r[1]), "=r"(r[2]), "=r"(r[3]) : "r"(a));
}
static __device__ __forceinline__ void mma16816(float c[4], const uint32_t a[4],
                                                uint32_t b0, uint32_t b1) {
    asm volatile(
        "mma.sync.aligned.m16n8k16.row.col.f32.f16.f16.f32 "
        "{%0,%1,%2,%3}, {%4,%5,%6,%7}, {%8,%9}, {%0,%1,%2,%3};"
        : "+f"(c[0]), "+f"(c[1]), "+f"(c[2]), "+f"(c[3])
        : "r"(a[0]), "r"(a[1]), "r"(a[2]), "r"(a[3]), "r"(b0), "r"(b1));
}
static __device__ __forceinline__ void splitstore(__half* hp, __half* lp,
                                                  float v0, float v1) {
    __half h0 = __float2half_rn(v0), h1 = __float2half_rn(v1);
    *(__half2*)hp = __halves2half2(h0, h1);
    *(__half2*)lp = __halves2half2(__float2half_rn(v0 - __half2float(h0)),
                                   __float2half_rn(v1 - __half2float(h1)));
}

enum { EPI_QK = 0, EPI_V, EPI_SCORE, EPI_PV, EPI_OUT };

// ---------------------------------------------------------------------------
// 128x128 NT GEMM, fp16 mma + ldmatrix, 3-stage cp.async, fused epilogue.
// NTERM=3: Ahi*Bhi + Ahi*Blo + Alo*Bhi ; NTERM=2: A*(Bhi+Blo) ; NTERM=1: A*B
// 256 thr = 8 warps (4m x 2n); warp 32x64.
// ---------------------------------------------------------------------------
template <int KTOT, int NTERM, int EPI>
__global__ __launch_bounds__(256) void gemm_kernel(float* outp)
{
    extern __shared__ __align__(128) __half sm[];
    const int NA = (NTERM == 3) ? 2 : 1;
    const int NB = (NTERM == 1) ? 1 : 2;
    const int NT = NA + NB;

    const int tid = threadIdx.x, warp = tid >> 5, lane = tid & 31;
    const int wm = (warp & 3) * 32, wn = (warp >> 2) * 64;
    const int m0 = blockIdx.y * 128, n0 = blockIdx.x * 128, z = blockIdx.z;

    const __half *Ahi, *Alo = nullptr, *Bhi, *Blo = nullptr;
    int lda, ldb;
    if (EPI == EPI_QK) {
        Ahi = g_xhi; Alo = g_xlo; lda = 1024;
        Bhi = g_wThi + (size_t)z * 1048576; Blo = g_wTlo + (size_t)z * 1048576; ldb = 1024;
    } else if (EPI == EPI_V) {
        Ahi = g_xhi; lda = 1024;
        Bhi = g_wThi + (size_t)2 * 1048576; Blo = g_wTlo + (size_t)2 * 1048576; ldb = 1024;
    } else if (EPI == EPI_SCORE) {
        Ahi = g_Qhi + (size_t)z * 2048 * 128; Alo = g_Qlo + (size_t)z * 2048 * 128; lda = 128;
        Bhi = g_Khi + (size_t)z * 2048 * 128; Blo = g_Klo + (size_t)z * 2048 * 128; ldb = 128;
    } else if (EPI == EPI_PV) {
        Ahi = g_P + (size_t)z * 2048 * 2048; lda = 2048;
        Bhi = g_Vthi + (size_t)z * 128 * 2048; ldb = 2048;
    } else {
        Ahi = g_Valshi; lda = 1024;
        Bhi = g_wThi + (size_t)3 * 1048576; Blo = g_wTlo + (size_t)3 * 1048576; ldb = 1024;
    }

    auto plane = [&](int st, int pl) -> __half* { return sm + (st * NT + pl) * PLANEH; };

    auto load_stage = [&](int st, int ch) {
        const int k0 = ch * 32;
#pragma unroll
        for (int r = 0; r < 2; ++r) {
            const int idx = tid + r * 256;
            const int row = idx >> 2, col = (idx & 3) * 8;
            cpa16(plane(st, 0) + row * SSTR + col, Ahi + (size_t)(m0 + row) * lda + k0 + col);
            if (NA == 2)
                cpa16(plane(st, 1) + row * SSTR + col, Alo + (size_t)(m0 + row) * lda + k0 + col);
            cpa16(plane(st, NA) + row * SSTR + col, Bhi + (size_t)(n0 + row) * ldb + k0 + col);
            if (NB == 2)
                cpa16(plane(st, NA + 1) + row * SSTR + col, Blo + (size_t)(n0 + row) * ldb + k0 + col);
        }
        asm volatile("cp.async.commit_group;" ::: "memory");
    };

    float c[2][8][4] = {};
    const int nCh = KTOT / 32;
    load_stage(0, 0);
    if (nCh > 1) load_stage(1, 1);

    const int lrow = lane & 15, lkh = (lane >> 4) * 8;

    for (int ch = 0; ch < nCh; ++ch) {
        if (ch + 2 < nCh) asm volatile("cp.async.wait_group 1;" ::: "memory");
        else              asm volatile("cp.async.wait_group 0;" ::: "memory");
        __syncthreads();
        const int buf = ch % 3;
        if (ch + 2 < nCh) load_stage((ch + 2) % 3, ch + 2);

#pragma unroll
        for (int s = 0; s < 2; ++s) {
            const int ks = s * 16;
            uint32_t a[2][2][4];
#pragma unroll
            for (int pa = 0; pa < NA; ++pa)
#pragma unroll
                for (int mt = 0; mt < 2; ++mt)
                    ldm4(a[pa][mt], plane(buf, pa) + (wm + mt * 16 + lrow) * SSTR + ks + lkh);
            uint32_t b[2][4][4];
#pragma unroll
            for (int pb = 0; pb < NB; ++pb)
#pragma unroll
                for (int np = 0; np < 4; ++np)
                    ldm4(b[pb][np], plane(buf, NA + pb) + (wn + np * 16 + lrow) * SSTR + ks + lkh);

            // term-major ordering: accumulator reuse distance = 16 MMAs
#pragma unroll
            for (int np = 0; np < 4; ++np)
#pragma unroll
                for (int mt = 0; mt < 2; ++mt) {
                    mma16816(c[mt][2 * np],     a[0][mt], b[0][np][0], b[0][np][2]);
                    mma16816(c[mt][2 * np + 1], a[0][mt], b[0][np][1], b[0][np][3]);
                }
            if (NB == 2) {
#pragma unroll
                for (int np = 0; np < 4; ++np)
#pragma unroll
                    for (int mt = 0; mt < 2; ++mt) {
                        mma16816(c[mt][2 * np],     a[0][mt], b[1][np][0], b[1][np][2]);
                        mma16816(c[mt][2 * np + 1], a[0][mt], b[1][np][1], b[1][np][3]);
                    }
            }
            if (NA == 2) {
#pragma unroll
                for (int np = 0; np < 4; ++np)
#pragma unroll
                    for (int mt = 0; mt < 2; ++mt) {
                        mma16816(c[mt][2 * np],     a[1][mt], b[0][np][0], b[0][np][2]);
                        mma16816(c[mt][2 * np + 1], a[1][mt], b[0][np][1], b[0][np][3]);
                    }
            }
        }
        __syncthreads();
    }

    // ---- epilogue: m = m0+wm+mt*16+lane/4+p*8 ; n = n0+wn+nt*8+(lane%4)*2 ----
#pragma unroll
    for (int mt = 0; mt < 2; ++mt)
#pragma unroll
        for (int nt = 0; nt < 8; ++nt)
#pragma unroll
            for (int p = 0; p < 2; ++p) {
                const int m = m0 + wm + mt * 16 + (lane >> 2) + p * 8;
                const int nl = wn + nt * 8 + (lane & 3) * 2;
                float v0 = c[mt][nt][2 * p], v1 = c[mt][nt][2 * p + 1];

                if (EPI == EPI_QK) {
                    const int b = m >> 11, s = m & 2047;
                    const int n = n0 + nl, h = n >> 6, d = n & 63;
                    const size_t base = ((size_t)(h * 2048 + s)) * 128 + b * 64 + d;
                    if (z == 1 && b == 1) { v0 = -v0; v1 = -v1; }
                    __half* Dh = (z == 0) ? g_Qhi : g_Khi;
                    __half* Dl = (z == 0) ? g_Qlo : g_Klo;
                    splitstore(&Dh[base], &Dl[base], v0, v1);
                } else if (EPI == EPI_V) {
                    const int b = m >> 11, s = m & 2047;
                    const int n = n0 + nl, h = n >> 6, d = n & 63;
                    *(float2*)&g_Vf[((size_t)(h * 2048 + s)) * 128 + b * 64 + d] =
                        make_float2(v0, v1);
                } else if (EPI == EPI_SCORE) {
                    float p0 = 1.f / (1.f + __expf(-v0 * 0.03125f));
                    float p1 = 1.f / (1.f + __expf(-v1 * 0.03125f));
                    *(__half2*)&g_P[((size_t)z * 2048 + m) * 2048 + n0 + nl] =
                        __halves2half2(__float2half_rn(p0), __float2half_rn(p1));
                } else if (EPI == EPI_PV) {
                    const int b = nl >> 6, d = nl & 63;
                    if (b) {
                        v0 = g_Colsum[z * 64 + d]     - v0;
                        v1 = g_Colsum[z * 64 + d + 1] - v1;
                    }
                    *(__half2*)&g_Valshi[((size_t)(b * 2048 + m)) * 1024 + z * 64 + d] =
                        __halves2half2(__float2half_rn(v0), __float2half_rn(v1));
                } else {
                    *(float2*)&outp[(size_t)m * 1024 + n0 + nl] = make_float2(v0, v1);
                }
            }
}

// ---------------------------------------------------------------------------
// prep kernels
// ---------------------------------------------------------------------------
__global__ __launch_bounds__(256) void split_x_kernel(const float* __restrict__ x)
{
    const size_t i = ((size_t)blockIdx.x * 256 + threadIdx.x) * 4;
    float4 v = *(const float4*)(x + i);
    splitstore(&g_xhi[i],     &g_xlo[i],     v.x, v.y);
    splitstore(&g_xhi[i + 2], &g_xlo[i + 2], v.z, v.w);
}

__global__ __launch_bounds__(256) void trw_kernel(
    const float* __restrict__ w0, const float* __restrict__ w1,
    const float* __restrict__ w2, const float* __restrict__ w3)
{
    const float* W = (blockIdx.z == 0) ? w0 : (blockIdx.z == 1) ? w1
                     : (blockIdx.z == 2) ? w2 : w3;
    __shared__ float t[32][33];
    const int bx = blockIdx.x * 32, by = blockIdx.y * 32;
    const int tx = threadIdx.x & 31, ty8 = threadIdx.x >> 5;
#pragma unroll
    for (int s = 0; s < 4; ++s)
        t[ty8 + s * 8][tx] = W[(size_t)(by + ty8 + s * 8) * 1024 + bx + tx];
    __syncthreads();
    __half* Dh = g_wThi + (size_t)blockIdx.z * 1048576;
    __half* Dl = g_wTlo + (size_t)blockIdx.z * 1048576;
#pragma unroll
    for (int s = 0; s < 4; ++s) {
        const int ty = ty8 + s * 8;
        const float v = t[tx][ty];
        const size_t o = (size_t)(bx + ty) * 1024 + by + tx;
        __half h = __float2half_rn(v);
        Dh[o] = h;
        Dl[o] = __float2half_rn(v - __half2float(h));
    }
}

// transpose V per (head, 128-s-chunk) + deterministic colsum partials of V1
__global__ __launch_bounds__(256) void trv_kernel()
{
    extern __shared__ float tl[];   // [128][129]
    const int sc = blockIdx.x, h = blockIdx.y;
    const int s0 = sc * 128;
    const float* V = g_Vf + ((size_t)h * 2048 + s0) * 128;

    for (int i = threadIdx.x; i < 128 * 128; i += 256)
        tl[(i >> 7) * 129 + (i & 127)] = V[i];
    __syncthreads();

    if (threadIdx.x < 64) {
        float acc = 0.f;
        for (int s = 0; s < 128; ++s) acc += tl[s * 129 + 64 + threadIdx.x];
        g_ColPart[((size_t)h * 16 + sc) * 64 + threadIdx.x] = acc;
    }

    const int dp = threadIdx.x & 127, seg = threadIdx.x >> 7;
    __half* Th = g_Vthi + ((size_t)h * 128 + dp) * 2048 + s0 + seg * 64;
#pragma unroll 8
    for (int j = 0; j < 64; ++j)
        Th[j] = __float2half_rn(tl[(seg * 64 + j) * 129 + dp]);
}

__global__ void redc_kernel()
{
    const int t = threadIdx.x;   // 1024 = 16h * 64d
    const int h = t >> 6, d = t & 63;
    float a = 0.f;
    for (int sc = 0; sc < 16; ++sc)
        a += g_ColPart[((size_t)h * 16 + sc) * 64 + d];
    g_Colsum[t] = a;
}

// ---------------------------------------------------------------------------
extern "C" void kernel_launch(void* const* d_in, const int* in_sizes, int n_in,
                              void* d_out, int out_size)
{
    const float* x  = (const float*)d_in[0];
    const float* wq = (const float*)d_in[1];
    const float* wk = (const float*)d_in[2];
    const float* wv = (const float*)d_in[3];
    const float* wo = (const float*)d_in[4];
    float* out = (float*)d_out;

    const int PB  = PLANEH * 2;          // plane bytes (10240)
    const int SM4 = 3 * 4 * PB;          // 122880 (NTERM=3)
    const int SM3 = 3 * 3 * PB;          //  92160 (NTERM=2)
    const int SM2 = 3 * 2 * PB;          //  61440 (NTERM=1)
    const int SMT = 128 * 129 * 4;       //  66048

    cudaFuncSetAttribute(gemm_kernel<1024, 3, EPI_QK>,    cudaFuncAttributeMaxDynamicSharedMemorySize, SM4);
    cudaFuncSetAttribute(gemm_kernel<1024, 2, EPI_V>,     cudaFuncAttributeMaxDynamicSharedMemorySize, SM3);
    cudaFuncSetAttribute(gemm_kernel<128,  3, EPI_SCORE>, cudaFuncAttributeMaxDynamicSharedMemorySize, SM4);
    cudaFuncSetAttribute(gemm_kernel<2048, 1, EPI_PV>,    cudaFuncAttributeMaxDynamicSharedMemorySize, SM2);
    cudaFuncSetAttribute(gemm_kernel<1024, 2, EPI_OUT>,   cudaFuncAttributeMaxDynamicSharedMemorySize, SM3);
    cudaFuncSetAttribute(trv_kernel,                      cudaFuncAttributeMaxDynamicSharedMemorySize, SMT);

    split_x_kernel<<<4096, 256>>>(x);
    trw_kernel<<<dim3(32, 32, 4), 256>>>(wq, wk, wv, wo);

    gemm_kernel<1024, 3, EPI_QK><<<dim3(8, 32, 2), 256, SM4>>>(nullptr);
    gemm_kernel<1024, 2, EPI_V><<<dim3(8, 32, 1), 256, SM3>>>(nullptr);

    trv_kernel<<<dim3(16, 16), 256, SMT>>>();
    redc_kernel<<<1, 1024>>>();

    gemm_kernel<128,  3, EPI_SCORE><<<dim3(16, 16, 16), 256, SM4>>>(nullptr);
    gemm_kernel<2048, 1, EPI_PV><<<dim3(1, 16, 16), 256, SM2>>>(nullptr);
    gemm_kernel<1024, 2, EPI_OUT><<<dim3(8, 32, 1), 256, SM3>>>(out);
}

// round 7
// speedup vs baseline: 3.6686x; 1.4726x over previous
#include <cuda_runtime.h>
#include <cuda_fp16.h>
#include <cstdint>

// ---------------------------------------------------------------------------
// B=2,S=2048,D=1024,H=16,HD=64, scale=32. softmax over batch (B=2) ==
//   P     = sigmoid((Q0K0^T - Q1K1^T)/32)   per head [2048x2048]
//   vals0 = P @ V0 ;  vals1 = colsum(V1) - P @ V1
// fp16 mma.sync m16n8k16 NT GEMMs; hi/lo split planes:
//   Q/K proj, score: 3-term | V proj, out: 2-term | PV: 1-term
// ---------------------------------------------------------------------------

__device__ __align__(128) __half g_xhi[4096 * 1024];
__device__ __align__(128) __half g_xlo[4096 * 1024];
__device__ __align__(128) __half g_wThi[4 * 1024 * 1024];   // [z][n][k]
__device__ __align__(128) __half g_wTlo[4 * 1024 * 1024];
__device__ __align__(128) __half g_Qhi[16 * 2048 * 128];    // [h][s][b*64+d]
__device__ __align__(128) __half g_Qlo[16 * 2048 * 128];
__device__ __align__(128) __half g_Khi[16 * 2048 * 128];    // K1 negated
__device__ __align__(128) __half g_Klo[16 * 2048 * 128];
__device__ __align__(128) float  g_Vf [16 * 2048 * 128];    // fp32 V [h][s][b*64+d]
__device__ __align__(128) __half g_Vthi[16 * 128 * 2048];   // [h][b*64+d][s]
__device__ __align__(128) __half g_P[(size_t)16 * 2048 * 2048];
__device__ __align__(128) __half g_Valshi[4096 * 1024];     // [b*2048+q][h*64+d]
__device__ float g_ColPart[16 * 16 * 64];
__device__ float g_Colsum[16 * 64];

#define SSTR   40                 // halfs per smem row, 32-K chunks (+8 pad)
#define PLANEH (128 * SSTR)       // 5120 halfs / 10240 B
#define ASTR   136                // halfs per row for resident 128-K planes

// ---------------------------------------------------------------------------
static __device__ __forceinline__ void cpa16(const __half* dst_smem, const void* src) {
    uint32_t d = (uint32_t)__cvta_generic_to_shared(dst_smem);
    asm volatile("cp.async.cg.shared.global [%0], [%1], 16;" :: "r"(d), "l"(src));
}
static __device__ __forceinline__ void ldm4(uint32_t r[4], const __half* p) {
    uint32_t a = (uint32_t)__cvta_generic_to_shared(p);
    asm volatile("ldmatrix.sync.aligned.m8n8.x4.shared.b16 {%0,%1,%2,%3}, [%4];"
                 : "=r"(r[0]), "=r"(r[1]), "=r"(r[2]), "=r"(r[3]) : "r"(a));
}
static __device__ __forceinline__ void mma16816(float c[4], const uint32_t a[4],
                                                uint32_t b0, uint32_t b1) {
    asm volatile(
        "mma.sync.aligned.m16n8k16.row.col.f32.f16.f16.f32 "
        "{%0,%1,%2,%3}, {%4,%5,%6,%7}, {%8,%9}, {%0,%1,%2,%3};"
        : "+f"(c[0]), "+f"(c[1]), "+f"(c[2]), "+f"(c[3])
        : "r"(a[0]), "r"(a[1]), "r"(a[2]), "r"(a[3]), "r"(b0), "r"(b1));
}
static __device__ __forceinline__ void splitstore(__half* hp, __half* lp,
                                                  float v0, float v1) {
    __half h0 = __float2half_rn(v0), h1 = __float2half_rn(v1);
    *(__half2*)hp = __halves2half2(h0, h1);
    *(__half2*)lp = __halves2half2(__float2half_rn(v0 - __half2float(h0)),
                                   __float2half_rn(v1 - __half2float(h1)));
}

enum { EPI_QK = 0, EPI_V, EPI_PV, EPI_OUT };

// ---------------------------------------------------------------------------
// 128x128 NT GEMM, fp16 mma + ldmatrix, NSTG-stage cp.async, fused epilogue.
// NTERM=3: Ahi*Bhi + Ahi*Blo + Alo*Bhi ; NTERM=2: A*(Bhi+Blo) ; NTERM=1: A*B
// ---------------------------------------------------------------------------
template <int KTOT, int NTERM, int EPI, int OCC, int NSTG>
__global__ __launch_bounds__(256, OCC) void gemm_kernel(float* outp)
{
    extern __shared__ __align__(128) __half sm[];
    const int NA = (NTERM == 3) ? 2 : 1;
    const int NB = (NTERM == 1) ? 1 : 2;
    const int NT = NA + NB;

    const int tid = threadIdx.x, warp = tid >> 5, lane = tid & 31;
    const int wm = (warp & 3) * 32, wn = (warp >> 2) * 64;
    const int m0 = blockIdx.y * 128, n0 = blockIdx.x * 128, z = blockIdx.z;

    const __half *Ahi, *Alo = nullptr, *Bhi, *Blo = nullptr;
    int lda, ldb;
    if (EPI == EPI_QK) {
        Ahi = g_xhi; Alo = g_xlo; lda = 1024;
        Bhi = g_wThi + (size_t)z * 1048576; Blo = g_wTlo + (size_t)z * 1048576; ldb = 1024;
    } else if (EPI == EPI_V) {
        Ahi = g_xhi; lda = 1024;
        Bhi = g_wThi + (size_t)2 * 1048576; Blo = g_wTlo + (size_t)2 * 1048576; ldb = 1024;
    } else if (EPI == EPI_PV) {
        Ahi = g_P + (size_t)z * 2048 * 2048; lda = 2048;
        Bhi = g_Vthi + (size_t)z * 128 * 2048; ldb = 2048;
    } else {
        Ahi = g_Valshi; lda = 1024;
        Bhi = g_wThi + (size_t)3 * 1048576; Blo = g_wTlo + (size_t)3 * 1048576; ldb = 1024;
    }

    auto plane = [&](int st, int pl) -> __half* { return sm + (st * NT + pl) * PLANEH; };

    auto load_stage = [&](int ch) {
        const int st = ch % NSTG, k0 = ch * 32;
#pragma unroll
        for (int r = 0; r < 2; ++r) {
            const int idx = tid + r * 256;
            const int row = idx >> 2, col = (idx & 3) * 8;
            cpa16(plane(st, 0) + row * SSTR + col, Ahi + (size_t)(m0 + row) * lda + k0 + col);
            if (NA == 2)
                cpa16(plane(st, 1) + row * SSTR + col, Alo + (size_t)(m0 + row) * lda + k0 + col);
            cpa16(plane(st, NA) + row * SSTR + col, Bhi + (size_t)(n0 + row) * ldb + k0 + col);
            if (NB == 2)
                cpa16(plane(st, NA + 1) + row * SSTR + col, Blo + (size_t)(n0 + row) * ldb + k0 + col);
        }
        asm volatile("cp.async.commit_group;" ::: "memory");
    };

    float c[2][8][4] = {};
    const int nCh = KTOT / 32;
    load_stage(0);
    if (NSTG == 3 && nCh > 1) load_stage(1);

    const int lrow = lane & 15, lkh = (lane >> 4) * 8;

    for (int ch = 0; ch < nCh; ++ch) {
        if (NSTG == 3) {
            if (ch + 1 < nCh) asm volatile("cp.async.wait_group 1;" ::: "memory");
            else              asm volatile("cp.async.wait_group 0;" ::: "memory");
            __syncthreads();
            if (ch + 2 < nCh) load_stage(ch + 2);
        } else {
            if (ch + 1 < nCh) {
                __syncthreads();
                load_stage(ch + 1);
                asm volatile("cp.async.wait_group 1;" ::: "memory");
            } else {
                asm volatile("cp.async.wait_group 0;" ::: "memory");
            }
            __syncthreads();
        }
        const int buf = ch % NSTG;

#pragma unroll
        for (int s = 0; s < 2; ++s) {
            const int ks = s * 16;
            uint32_t a[2][2][4];
#pragma unroll
            for (int pa = 0; pa < NA; ++pa)
#pragma unroll
                for (int mt = 0; mt < 2; ++mt)
                    ldm4(a[pa][mt], plane(buf, pa) + (wm + mt * 16 + lrow) * SSTR + ks + lkh);
#pragma unroll
            for (int np = 0; np < 4; ++np) {
                uint32_t b[4];
                ldm4(b, plane(buf, NA) + (wn + np * 16 + lrow) * SSTR + ks + lkh);
#pragma unroll
                for (int mt = 0; mt < 2; ++mt) {
                    mma16816(c[mt][2 * np],     a[0][mt], b[0], b[2]);
                    mma16816(c[mt][2 * np + 1], a[0][mt], b[1], b[3]);
                }
            }
            if (NB == 2) {
#pragma unroll
                for (int np = 0; np < 4; ++np) {
                    uint32_t b[4];
                    ldm4(b, plane(buf, NA + 1) + (wn + np * 16 + lrow) * SSTR + ks + lkh);
#pragma unroll
                    for (int mt = 0; mt < 2; ++mt) {
                        mma16816(c[mt][2 * np],     a[0][mt], b[0], b[2]);
                        mma16816(c[mt][2 * np + 1], a[0][mt], b[1], b[3]);
                    }
                }
            }
            if (NA == 2) {
#pragma unroll
                for (int np = 0; np < 4; ++np) {
                    uint32_t b[4];
                    ldm4(b, plane(buf, NA) + (wn + np * 16 + lrow) * SSTR + ks + lkh);
#pragma unroll
                    for (int mt = 0; mt < 2; ++mt) {
                        mma16816(c[mt][2 * np],     a[1][mt], b[0], b[2]);
                        mma16816(c[mt][2 * np + 1], a[1][mt], b[1], b[3]);
                    }
                }
            }
        }
    }

    // ---- epilogue: m = m0+wm+mt*16+lane/4+p*8 ; n = n0+wn+nt*8+(lane%4)*2 ----
#pragma unroll
    for (int mt = 0; mt < 2; ++mt)
#pragma unroll
        for (int nt = 0; nt < 8; ++nt)
#pragma unroll
            for (int p = 0; p < 2; ++p) {
                const int m = m0 + wm + mt * 16 + (lane >> 2) + p * 8;
                const int nl = wn + nt * 8 + (lane & 3) * 2;
                float v0 = c[mt][nt][2 * p], v1 = c[mt][nt][2 * p + 1];

                if (EPI == EPI_QK) {
                    const int b = m >> 11, s = m & 2047;
                    const int n = n0 + nl, h = n >> 6, d = n & 63;
                    const size_t base = ((size_t)(h * 2048 + s)) * 128 + b * 64 + d;
                    if (z == 1 && b == 1) { v0 = -v0; v1 = -v1; }
                    __half* Dh = (z == 0) ? g_Qhi : g_Khi;
                    __half* Dl = (z == 0) ? g_Qlo : g_Klo;
                    splitstore(&Dh[base], &Dl[base], v0, v1);
                } else if (EPI == EPI_V) {
                    const int b = m >> 11, s = m & 2047;
                    const int n = n0 + nl, h = n >> 6, d = n & 63;
                    *(float2*)&g_Vf[((size_t)(h * 2048 + s)) * 128 + b * 64 + d] =
                        make_float2(v0, v1);
                } else if (EPI == EPI_PV) {
                    const int b = nl >> 6, d = nl & 63;
                    if (b) {
                        v0 = g_Colsum[z * 64 + d]     - v0;
                        v1 = g_Colsum[z * 64 + d + 1] - v1;
                    }
                    *(__half2*)&g_Valshi[((size_t)(b * 2048 + m)) * 1024 + z * 64 + d] =
                        __halves2half2(__float2half_rn(v0), __float2half_rn(v1));
                } else {
                    *(float2*)&outp[(size_t)m * 1024 + n0 + nl] = make_float2(v0, v1);
                }
            }
}

// ---------------------------------------------------------------------------
// Score kernel: Q hi/lo resident in smem; stream K hi/lo over 4 n-tiles.
// P = sigmoid(S/32) via f16x2 ex2+rcp.  Grid (4, 16, 16) = (n-group, m, h).
// ---------------------------------------------------------------------------
__global__ __launch_bounds__(256) void score_kernel()
{
    extern __shared__ __align__(128) __half sm[];
    __half* Aq[2] = { sm, sm + 128 * ASTR };
    __half* Bb    = sm + 2 * 128 * ASTR;
    auto bplane = [&](int st, int pl) -> __half* { return Bb + (st * 2 + pl) * PLANEH; };

    const int tid = threadIdx.x, warp = tid >> 5, lane = tid & 31;
    const int wm = (warp & 3) * 32, wn = (warp >> 2) * 64;
    const int h = blockIdx.z, m0 = blockIdx.y * 128, nb = blockIdx.x * 512;

    const __half* Qh = g_Qhi + (size_t)h * 2048 * 128 + (size_t)m0 * 128;
    const __half* Ql = g_Qlo + (size_t)h * 2048 * 128 + (size_t)m0 * 128;
    const __half* Kh = g_Khi + (size_t)h * 2048 * 128;
    const __half* Kl = g_Klo + (size_t)h * 2048 * 128;

    // resident A: 128x128 per plane (8 rounds x 16B x 2 planes)
#pragma unroll
    for (int r = 0; r < 8; ++r) {
        const int idx = tid + r * 256;
        const int row = idx >> 4, col = (idx & 15) * 8;
        cpa16(Aq[0] + row * ASTR + col, Qh + row * 128 + col);
        cpa16(Aq[1] + row * ASTR + col, Ql + row * 128 + col);
    }
    asm volatile("cp.async.commit_group;" ::: "memory");

    auto loadB = [&](int g) {
        const int st = g % 3, ntl = g >> 2, k0 = (g & 3) * 32;
#pragma unroll
        for (int r = 0; r < 2; ++r) {
            const int idx = tid + r * 256;
            const int row = idx >> 2, col = (idx & 3) * 8;
            const size_t src = (size_t)(nb + ntl * 128 + row) * 128 + k0 + col;
            cpa16(bplane(st, 0) + row * SSTR + col, Kh + src);
            cpa16(bplane(st, 1) + row * SSTR + col, Kl + src);
        }
        asm volatile("cp.async.commit_group;" ::: "memory");
    };

    loadB(0); loadB(1);
    float c[2][8][4] = {};
    const int lrow = lane & 15, lkh = (lane >> 4) * 8;
    const __half2 one2 = __float2half2_rn(1.0f);
    const float NK = -0.04508422f;   // -log2(e)/32

    const int G = 16;   // 4 n-tiles x 4 chunks
    for (int g = 0; g < G; ++g) {
        if (g + 1 < G) asm volatile("cp.async.wait_group 1;" ::: "memory");
        else           asm volatile("cp.async.wait_group 0;" ::: "memory");
        __syncthreads();
        if (g + 2 < G) loadB(g + 2);

        const int st = g % 3, ch = g & 3;
#pragma unroll
        for (int s = 0; s < 2; ++s) {
            const int kA = ch * 32 + s * 16 + lkh;
            const int ks = s * 16;
            uint32_t a[2][2][4];
#pragma unroll
            for (int pa = 0; pa < 2; ++pa)
#pragma unroll
                for (int mt = 0; mt < 2; ++mt)
                    ldm4(a[pa][mt], Aq[pa] + (wm + mt * 16 + lrow) * ASTR + kA);
#pragma unroll
            for (int np = 0; np < 4; ++np) {
                uint32_t b[4];
                ldm4(b, bplane(st, 0) + (wn + np * 16 + lrow) * SSTR + ks + lkh);
#pragma unroll
                for (int mt = 0; mt < 2; ++mt) {
                    mma16816(c[mt][2 * np],     a[0][mt], b[0], b[2]);
                    mma16816(c[mt][2 * np + 1], a[0][mt], b[1], b[3]);
                }
            }
#pragma unroll
            for (int np = 0; np < 4; ++np) {
                uint32_t b[4];
                ldm4(b, bplane(st, 1) + (wn + np * 16 + lrow) * SSTR + ks + lkh);
#pragma unroll
                for (int mt = 0; mt < 2; ++mt) {
                    mma16816(c[mt][2 * np],     a[0][mt], b[0], b[2]);
                    mma16816(c[mt][2 * np + 1], a[0][mt], b[1], b[3]);
                }
            }
#pragma unroll
            for (int np = 0; np < 4; ++np) {
                uint32_t b[4];
                ldm4(b, bplane(st, 0) + (wn + np * 16 + lrow) * SSTR + ks + lkh);
#pragma unroll
                for (int mt = 0; mt < 2; ++mt) {
                    mma16816(c[mt][2 * np],     a[1][mt], b[0], b[2]);
                    mma16816(c[mt][2 * np + 1], a[1][mt], b[1], b[3]);
                }
            }
        }

        if (ch == 3) {   // epilogue for finished n-tile
            const int ntl = g >> 2;
#pragma unroll
            for (int mt = 0; mt < 2; ++mt)
#pragma unroll
                for (int nt = 0; nt < 8; ++nt)
#pragma unroll
                    for (int p = 0; p < 2; ++p) {
                        const int m = m0 + wm + mt * 16 + (lane >> 2) + p * 8;
                        const int n = nb + ntl * 128 + wn + nt * 8 + (lane & 3) * 2;
                        __half2 m2 = __floats2half2_rn(c[mt][nt][2 * p] * NK,
                                                       c[mt][nt][2 * p + 1] * NK);
                        __half2 P2 = h2rcp(__hadd2(one2, h2exp2(m2)));
                        *(__half2*)&g_P[((size_t)h * 2048 + m) * 2048 + n] = P2;
                        c[mt][nt][2 * p] = 0.f; c[mt][nt][2 * p + 1] = 0.f;
                    }
        }
    }
}

// ---------------------------------------------------------------------------
// prep kernels
// ---------------------------------------------------------------------------
__global__ __launch_bounds__(256) void split_x_kernel(const float* __restrict__ x)
{
    const size_t i = ((size_t)blockIdx.x * 256 + threadIdx.x) * 4;
    float4 v = *(const float4*)(x + i);
    splitstore(&g_xhi[i],     &g_xlo[i],     v.x, v.y);
    splitstore(&g_xhi[i + 2], &g_xlo[i + 2], v.z, v.w);
}

__global__ __launch_bounds__(256) void trw_kernel(
    const float* __restrict__ w0, const float* __restrict__ w1,
    const float* __restrict__ w2, const float* __restrict__ w3)
{
    const float* W = (blockIdx.z == 0) ? w0 : (blockIdx.z == 1) ? w1
                     : (blockIdx.z == 2) ? w2 : w3;
    __shared__ float t[32][33];
    const int bx = blockIdx.x * 32, by = blockIdx.y * 32;
    const int tx = threadIdx.x & 31, ty8 = threadIdx.x >> 5;
#pragma unroll
    for (int s = 0; s < 4; ++s)
        t[ty8 + s * 8][tx] = W[(size_t)(by + ty8 + s * 8) * 1024 + bx + tx];
    __syncthreads();
    __half* Dh = g_wThi + (size_t)blockIdx.z * 1048576;
    __half* Dl = g_wTlo + (size_t)blockIdx.z * 1048576;
#pragma unroll
    for (int s = 0; s < 4; ++s) {
        const int ty = ty8 + s * 8;
        const float v = t[tx][ty];
        const size_t o = (size_t)(bx + ty) * 1024 + by + tx;
        __half h = __float2half_rn(v);
        Dh[o] = h;
        Dl[o] = __float2half_rn(v - __half2float(h));
    }
}

__global__ __launch_bounds__(256) void trv_kernel()
{
    extern __shared__ float tl[];   // [128][129]
    const int sc = blockIdx.x, h = blockIdx.y;
    const int s0 = sc * 128;
    const float* V = g_Vf + ((size_t)h * 2048 + s0) * 128;

    for (int i = threadIdx.x; i < 128 * 128; i += 256)
        tl[(i >> 7) * 129 + (i & 127)] = V[i];
    __syncthreads();

    if (threadIdx.x < 64) {
        float acc = 0.f;
        for (int s = 0; s < 128; ++s) acc += tl[s * 129 + 64 + threadIdx.x];
        g_ColPart[((size_t)h * 16 + sc) * 64 + threadIdx.x] = acc;
    }

    const int dp = threadIdx.x & 127, seg = threadIdx.x >> 7;
    __half* Th = g_Vthi + ((size_t)h * 128 + dp) * 2048 + s0 + seg * 64;
#pragma unroll 8
    for (int j = 0; j < 64; ++j)
        Th[j] = __float2half_rn(tl[(seg * 64 + j) * 129 + dp]);
}

__global__ void redc_kernel()
{
    const int t = threadIdx.x;   // 1024 = 16h * 64d
    const int h = t >> 6, d = t & 63;
    float a = 0.f;
    for (int sc = 0; sc < 16; ++sc)
        a += g_ColPart[((size_t)h * 16 + sc) * 64 + d];
    g_Colsum[t] = a;
}

// ---------------------------------------------------------------------------
extern "C" void kernel_launch(void* const* d_in, const int* in_sizes, int n_in,
                              void* d_out, int out_size)
{
    const float* x  = (const float*)d_in[0];
    const float* wq = (const float*)d_in[1];
    const float* wk = (const float*)d_in[2];
    const float* wv = (const float*)d_in[3];
    const float* wo = (const float*)d_in[4];
    float* out = (float*)d_out;

    const int PB    = PLANEH * 2;                         // 10240 B / plane
    const int SM_QK = 2 * 4 * PB;                         //  81920 (3-term, 2-stage)
    const int SM_V  = 3 * 3 * PB;                         //  92160 (2-term, 3-stage)
    const int SM_PV = 3 * 2 * PB;                         //  61440 (1-term, 3-stage)
    const int SM_SC = 2 * 128 * ASTR * 2 + 3 * 2 * PB;    // 131072 (score)
    const int SMT   = 128 * 129 * 4;                      //  66048

    cudaFuncSetAttribute(gemm_kernel<1024, 3, EPI_QK,  2, 2>, cudaFuncAttributeMaxDynamicSharedMemorySize, SM_QK);
    cudaFuncSetAttribute(gemm_kernel<1024, 2, EPI_V,   2, 3>, cudaFuncAttributeMaxDynamicSharedMemorySize, SM_V);
    cudaFuncSetAttribute(gemm_kernel<2048, 1, EPI_PV,  2, 3>, cudaFuncAttributeMaxDynamicSharedMemorySize, SM_PV);
    cudaFuncSetAttribute(gemm_kernel<1024, 2, EPI_OUT, 2, 3>, cudaFuncAttributeMaxDynamicSharedMemorySize, SM_V);
    cudaFuncSetAttribute(score_kernel, cudaFuncAttributeMaxDynamicSharedMemorySize, SM_SC);
    cudaFuncSetAttribute(trv_kernel,   cudaFuncAttributeMaxDynamicSharedMemorySize, SMT);

    split_x_kernel<<<4096, 256>>>(x);
    trw_kernel<<<dim3(32, 32, 4), 256>>>(wq, wk, wv, wo);

    gemm_kernel<1024, 3, EPI_QK, 2, 2><<<dim3(8, 32, 2), 256, SM_QK>>>(nullptr);
    gemm_kernel<1024, 2, EPI_V,  2, 3><<<dim3(8, 32, 1), 256, SM_V>>>(nullptr);

    trv_kernel<<<dim3(16, 16), 256, SMT>>>();
    redc_kernel<<<1, 1024>>>();

    score_kernel<<<dim3(4, 16, 16), 256, SM_SC>>>();
    gemm_kernel<2048, 1, EPI_PV, 2, 3><<<dim3(1, 16, 16), 256, SM_PV>>>(nullptr);
    gemm_kernel<1024, 2, EPI_OUT, 2, 3><<<dim3(8, 32, 1), 256, SM_V>>>(out);
}